// round 1
// baseline (speedup 1.0000x reference)
#include <cuda_runtime.h>

// WordEmbeddingModule: B=32768 words, LMAX=24, M=10, D=300, V=36.
// out[b, m, :] =
//   L <  M, m <  L : emb_table[tokens[b,m]]
//   L <  M, m >= L : pad_table[0]
//   L >= M         : lerp(emb[tok[lo]], emb[tok[hi]], w),
//                    pos = m*(L-1)/(M-1), lo=floor(pos), hi=min(lo+1,L-1), w=pos-lo
//
// Store-bound: 393 MB output. One CTA per word; threads 0..9 build per-row
// (tok_lo, tok_hi, w) metadata in smem, then 256 threads stream 750 float4
// stores per word (fully coalesced). Table gathers are L1-resident.

#define B_WORDS 32768
#define LMAX    24
#define M_OUT   10
#define D_DIM   300
#define D_VEC   (D_DIM / 4)          // 75 float4 per row
#define VEC_PER_WORD (M_OUT * D_VEC) // 750 float4 per word

__global__ __launch_bounds__(256, 8)
void word_embed_kernel(const float* __restrict__ emb_table,   // [36, 300]
                       const float* __restrict__ pad_table,   // [1, 300]
                       const int*   __restrict__ tokens,      // [B, 24]
                       const int*   __restrict__ lengths,     // [B]
                       float*       __restrict__ out)         // [B, 10, 300]
{
    const int b   = blockIdx.x;
    const int tid = threadIdx.x;

    __shared__ int   s_lo[M_OUT];
    __shared__ int   s_hi[M_OUT];
    __shared__ float s_w[M_OUT];

    if (tid < M_OUT) {
        const int m = tid;
        const int L = __ldg(lengths + b);
        int   tlo, thi;
        float w;
        if (L < M_OUT) {
            if (m < L) {
                tlo = __ldg(tokens + b * LMAX + m);
                thi = tlo;
                w   = 0.0f;
            } else {
                tlo = -1;   // pad row
                thi = -1;
                w   = 0.0f;
            }
        } else {
            // pos = m * (L-1) / (M-1), fp32 like the reference
            const float pos = (float)m * (float)(L - 1) / 9.0f;
            int lo = (int)floorf(pos);
            int hi = min(lo + 1, L - 1);
            w   = pos - (float)lo;
            tlo = __ldg(tokens + b * LMAX + lo);
            thi = __ldg(tokens + b * LMAX + hi);
        }
        s_lo[m] = tlo;
        s_hi[m] = thi;
        s_w[m]  = w;
    }
    __syncthreads();

    const float4* __restrict__ embv = (const float4*)emb_table;  // [36, 75]
    const float4* __restrict__ padv = (const float4*)pad_table;  // [75]
    float4* __restrict__ outv = (float4*)out + (size_t)b * VEC_PER_WORD;

    #pragma unroll
    for (int idx = tid; idx < VEC_PER_WORD; idx += 256) {
        const int m  = idx / D_VEC;
        const int d4 = idx - m * D_VEC;

        const int tlo = s_lo[m];
        float4 r;
        if (tlo < 0) {
            r = __ldg(padv + d4);
        } else {
            const float w  = s_w[m];
            const float iw = 1.0f - w;
            const float4 a = __ldg(embv + tlo * D_VEC + d4);
            const float4 c = __ldg(embv + s_hi[m] * D_VEC + d4);  // L1 hit; == a when w==0
            r.x = a.x * iw + c.x * w;
            r.y = a.y * iw + c.y * w;
            r.z = a.z * iw + c.z * w;
            r.w = a.w * iw + c.w * w;
        }
        outv[idx] = r;
    }
}

extern "C" void kernel_launch(void* const* d_in, const int* in_sizes, int n_in,
                              void* d_out, int out_size)
{
    const float* emb_table = (const float*)d_in[0];  // [36, 300] f32
    const float* pad_table = (const float*)d_in[1];  // [1, 300]  f32
    const int*   tokens    = (const int*)  d_in[2];  // [32768, 24] i32
    const int*   lengths   = (const int*)  d_in[3];  // [32768]     i32
    float*       out       = (float*)d_out;          // [32768, 10, 300] f32

    word_embed_kernel<<<B_WORDS, 256>>>(emb_table, pad_table, tokens, lengths, out);
}

// round 3
// speedup vs baseline: 1.3503x; 1.3503x over previous
#include <cuda_runtime.h>

// WordEmbeddingModule: B=32768 words, LMAX=24, M=10, D=300, V=36.
// out[b, m, :] =
//   L <  M, m <  L : emb_table[tokens[b,m]]
//   L <  M, m >= L : pad_table[0]
//   L >= M         : lerp(emb[tok[lo]], emb[tok[hi]], w),
//                    pos = m*(L-1)/(M-1), lo=floor(pos), hi=min(lo+1,L-1), w=pos-lo
//
// HBM-store-bound (393 MB out). R1 ncu: L1tex 62% was binding (6 wavefronts per
// float4: 3 scalar LDS + 2 LDG + 1 STG). R2: pack row metadata into one float4
// (1 LDS.128), skip the hi-gather when w==0 (~50% of elements), streaming stores.

#define B_WORDS 32768
#define LMAX    24
#define M_OUT   10
#define D_VEC   75                    // 300 floats / 4 = 75 float4 per row
#define VEC_PER_WORD (M_OUT * D_VEC)  // 750 float4 per word

__global__ __launch_bounds__(256, 8)
void word_embed_kernel(const float* __restrict__ emb_table,   // [36, 300]
                       const float* __restrict__ pad_table,   // [1, 300]
                       const int*   __restrict__ tokens,      // [B, 24]
                       const int*   __restrict__ lengths,     // [B]
                       float*       __restrict__ out)         // [B, 10, 300]
{
    const int b   = blockIdx.x;
    const int tid = threadIdx.x;

    // Per-row metadata: {lo_vec_off (int bits), hi_vec_off (int bits), w, 1-w}
    // lo_vec_off = token_lo * 75  (float4 index into emb table); -1 => pad row.
    __shared__ float4 s_meta[M_OUT];

    if (tid < M_OUT) {
        const int m = tid;
        const int L = __ldg(lengths + b);
        int   lo75, hi75;
        float w;
        if (L < M_OUT) {
            if (m < L) {
                lo75 = __ldg(tokens + b * LMAX + m) * D_VEC;
            } else {
                lo75 = -1;   // pad row
            }
            hi75 = lo75;
            w    = 0.0f;
        } else {
            // pos = m * (L-1) / (M-1), fp32 exactly as the reference
            const float pos = (float)m * (float)(L - 1) / 9.0f;
            int lo = (int)floorf(pos);
            int hi = min(lo + 1, L - 1);
            w    = pos - (float)lo;
            lo75 = __ldg(tokens + b * LMAX + lo) * D_VEC;
            hi75 = (w != 0.0f) ? __ldg(tokens + b * LMAX + hi) * D_VEC : lo75;
        }
        s_meta[m] = make_float4(__int_as_float(lo75), __int_as_float(hi75),
                                w, 1.0f - w);
    }
    __syncthreads();

    const float4* __restrict__ embv = (const float4*)emb_table;  // [36, 75]
    const float4* __restrict__ padv = (const float4*)pad_table;  // [75]
    float4* __restrict__ outv = (float4*)out + (size_t)b * VEC_PER_WORD;

    #pragma unroll
    for (int k = 0; k < 3; k++) {
        const int idx = tid + k * 256;
        if (k < 2 || idx < VEC_PER_WORD) {
            const int m  = idx / D_VEC;       // const-div: mulhi+shift
            const int d4 = idx - m * D_VEC;

            const float4 meta = s_meta[m];    // one LDS.128
            const int lo75 = __float_as_int(meta.x);

            float4 r;
            if (lo75 < 0) {
                r = __ldg(padv + d4);                       // pad row (L1 hit)
            } else {
                const float4 a = __ldg(embv + lo75 + d4);   // L1 hit
                r = a;
                const float w = meta.z;
                if (w != 0.0f) {                            // ~50% of elements
                    const int hi75 = __float_as_int(meta.y);
                    const float4 c = __ldg(embv + hi75 + d4);
                    const float iw = meta.w;
                    r.x = a.x * iw + c.x * w;
                    r.y = a.y * iw + c.y * w;
                    r.z = a.z * iw + c.z * w;
                    r.w = a.w * iw + c.w * w;
                }
            }
            __stcs(outv + idx, r);   // streaming store: write-once, evict-first
        }
    }
}

extern "C" void kernel_launch(void* const* d_in, const int* in_sizes, int n_in,
                              void* d_out, int out_size)
{
    const float* emb_table = (const float*)d_in[0];  // [36, 300] f32
    const float* pad_table = (const float*)d_in[1];  // [1, 300]  f32
    const int*   tokens    = (const int*)  d_in[2];  // [32768, 24] i32
    const int*   lengths   = (const int*)  d_in[3];  // [32768]     i32
    float*       out       = (float*)d_out;          // [32768, 10, 300] f32

    word_embed_kernel<<<B_WORDS, 256>>>(emb_table, pad_table, tokens, lengths, out);
}